// round 5
// baseline (speedup 1.0000x reference)
#include <cuda_runtime.h>
#include <math.h>
#include <stdint.h>

#define Bn 16
#define Cn 64
#define Hn 128
#define Wn 128
#define MXn 24
#define MYn 24
#define HIDn 32

// ---------------- scratch (device globals; no runtime allocation) ----------
__device__ float g_xw_re[Bn*Cn*Hn*MYn];       // [b][c][h][ky]
__device__ float g_xw_im[Bn*Cn*Hn*MYn];
__device__ float g_xft_re[MXn*MYn*Bn*Cn];     // [(kx*24+ky)][b][c]
__device__ float g_xft_im[MXn*MYn*Bn*Cn];
__device__ float g_oft_re[MXn*MYn*Bn*Cn];     // [(kx*24+ky)][b][o]
__device__ float g_oft_im[MXn*MYn*Bn*Cn];
__device__ float g_S_re[Bn*Hn*Cn*MYn];        // [b][h][o][ky]  (scaled)
__device__ float g_S_im[Bn*Hn*Cn*MYn];
__device__ float g_cos[MYn*Wn];               // cos(2*pi*k*w/128)
__device__ float g_sin[MYn*Wn];               // sin(2*pi*k*w/128)
__device__ float g_twT[Wn*48];                // [w][j] j<24: cos, j>=24: -sin

// ---------------- packed f32x2 helpers ----------------
__device__ __forceinline__ float2 ffma2(float2 a, float2 b, float2 c) {
    float2 r;
    asm("fma.rn.f32x2 %0, %1, %2, %3;"
        : "=l"(reinterpret_cast<unsigned long long&>(r))
        : "l"(reinterpret_cast<unsigned long long&>(a)),
          "l"(reinterpret_cast<unsigned long long&>(b)),
          "l"(reinterpret_cast<unsigned long long&>(c)));
    return r;
}
__device__ __forceinline__ float2 dup2(float x) { return make_float2(x, x); }

__device__ __forceinline__ float gelu_f(float v) {
    return 0.5f*v*(1.0f + erff(v*0.7071067811865476f));
}

// tf32 helpers
__device__ __forceinline__ float tf32f(float x) {
    uint32_t u;
    asm("cvt.rna.tf32.f32 %0, %1;" : "=r"(u) : "f"(x));
    return __uint_as_float(u);
}
__device__ __forceinline__ uint32_t fbits(float x) { return __float_as_uint(x); }

// mma.sync m16n8k8 tf32: D += A*B (D,C fp32)
__device__ __forceinline__ void mma8(float* d,
                                     uint32_t a0, uint32_t a1, uint32_t a2, uint32_t a3,
                                     uint32_t b0, uint32_t b1) {
    asm volatile(
        "mma.sync.aligned.m16n8k8.row.col.f32.tf32.tf32.f32 "
        "{%0,%1,%2,%3},{%4,%5,%6,%7},{%8,%9},{%0,%1,%2,%3};"
        : "+f"(d[0]), "+f"(d[1]), "+f"(d[2]), "+f"(d[3])
        : "r"(a0), "r"(a1), "r"(a2), "r"(a3), "r"(b0), "r"(b1));
}

// ---------------- K0: twiddle init ----------------
__global__ void k0_init() {
    int i = blockIdx.x*blockDim.x + threadIdx.x;
    if (i >= MYn*Wn) return;
    int k = i / Wn, w = i % Wn;
    float s, c;
    sincospif((float)(k*w) / 64.0f, &s, &c);
    g_cos[k*Wn + w] = c;
    g_sin[k*Wn + w] = s;
    g_twT[w*48 + k]      = c;
    g_twT[w*48 + 24 + k] = -s;
}

// ---------------- K1: partial DFT over W (ffma2 on row pairs) -------------
__global__ void __launch_bounds__(384) k1_dftW(const float* __restrict__ x) {
    __shared__ float Xs[32*132];
    __shared__ float Tw[32*48];
    int tid = threadIdx.x;
    int rg = tid & 31;
    int jg = tid >> 5;
    int row0 = blockIdx.x * 128;

    float2 acc[2][4];
    #pragma unroll
    for (int i = 0; i < 2; i++)
        #pragma unroll
        for (int j = 0; j < 4; j++) acc[i][j] = make_float2(0.f, 0.f);

    for (int kt = 0; kt < 4; kt++) {
        for (int i = tid; i < 4096; i += 384) {
            int r = i >> 5, w = i & 31;
            Xs[w*132 + r] = x[(size_t)(row0 + r)*128 + kt*32 + w];
        }
        for (int i = tid; i < 32*48; i += 384)
            Tw[i] = g_twT[kt*32*48 + i];
        __syncthreads();
        #pragma unroll
        for (int kk = 0; kk < 32; kk++) {
            float4 xa = *(const float4*)&Xs[kk*132 + 4*rg];
            float2 xp0 = make_float2(xa.x, xa.y);
            float2 xp1 = make_float2(xa.z, xa.w);
            float4 tq = *(const float4*)&Tw[kk*48 + 4*jg];
            float tv[4] = { tq.x, tq.y, tq.z, tq.w };
            #pragma unroll
            for (int j = 0; j < 4; j++) {
                float2 td = dup2(tv[j]);
                acc[0][j] = ffma2(xp0, td, acc[0][j]);
                acc[1][j] = ffma2(xp1, td, acc[1][j]);
            }
        }
        __syncthreads();
    }

    float* dst = (jg < 6) ? g_xw_re : g_xw_im;
    int col = (jg < 6) ? (4*jg) : (4*jg - 24);
    #pragma unroll
    for (int i = 0; i < 4; i++) {
        int pair = i >> 1, half = i & 1;
        float v0 = half ? acc[pair][0].y : acc[pair][0].x;
        float v1 = half ? acc[pair][1].y : acc[pair][1].x;
        float v2 = half ? acc[pair][2].y : acc[pair][2].x;
        float v3 = half ? acc[pair][3].y : acc[pair][3].x;
        int r = row0 + 4*rg + i;
        *(float4*)&dst[(size_t)r*24 + col] = make_float4(v0, v1, v2, v3);
    }
}

// ---------------- K2: partial DFT over H (ffma2 on re/im) -----------------
__global__ void __launch_bounds__(288) k2_dftH() {
    __shared__ float xr[128*24], xi[128*24];
    __shared__ float cs[24*128], sn[24*128];
    int bc = blockIdx.x;
    int tid = threadIdx.x;
    size_t base = (size_t)bc * (128*24);
    for (int i = tid; i < 3072; i += 288) {
        xr[i] = g_xw_re[base + i];
        xi[i] = g_xw_im[base + i];
        cs[i] = g_cos[i];
        sn[i] = g_sin[i];
    }
    __syncthreads();

    int ky  = tid % 24;
    int kxg = tid / 24;
    int kx0 = 2*kxg, kx1 = 2*kxg + 1;
    float2 acc0 = make_float2(0.f, 0.f);
    float2 acc1 = make_float2(0.f, 0.f);
    #pragma unroll 4
    for (int h = 0; h < 128; h++) {
        float a = xr[h*24 + ky];
        float b = xi[h*24 + ky];
        float2 ab  = make_float2(a, b);
        float2 bna = make_float2(b, -a);
        acc0 = ffma2(ab,  dup2(cs[kx0*128 + h]), acc0);
        acc0 = ffma2(bna, dup2(sn[kx0*128 + h]), acc0);
        acc1 = ffma2(ab,  dup2(cs[kx1*128 + h]), acc1);
        acc1 = ffma2(bna, dup2(sn[kx1*128 + h]), acc1);
    }
    int b = bc >> 6, c = bc & 63;
    int m0 = kx0*24 + ky, m1 = kx1*24 + ky;
    g_xft_re[(m0*Bn + b)*Cn + c] = acc0.x;
    g_xft_im[(m0*Bn + b)*Cn + c] = acc0.y;
    g_xft_re[(m1*Bn + b)*Cn + c] = acc1.x;
    g_xft_im[(m1*Bn + b)*Cn + c] = acc1.y;
}

// ---------------- K3: per-mode complex channel mix (512 thr) --------------
__global__ void __launch_bounds__(512) k3_mix(const float* __restrict__ wr_g,
                                              const float* __restrict__ wi_g) {
    __shared__ float xr_s[1024], xi_s[1024];
    __shared__ float wr_s[4096], wi_s[4096];
    int m = blockIdx.x, tid = threadIdx.x;
    for (int i = tid; i < 1024; i += 512) {
        xr_s[i] = g_xft_re[m*1024 + i];
        xi_s[i] = g_xft_im[m*1024 + i];
    }
    for (int i = tid; i < 4096; i += 512) {
        wr_s[i] = wr_g[(size_t)m*4096 + i];
        wi_s[i] = wi_g[(size_t)m*4096 + i];
    }
    __syncthreads();

    int b  = tid >> 5;
    int og = tid & 31;
    float2 re = make_float2(0.f, 0.f), im = make_float2(0.f, 0.f);
    #pragma unroll 4
    for (int c = 0; c < 64; c++) {
        float xr = xr_s[b*64 + c];
        float xi = xi_s[b*64 + c];
        float2 wr = *(const float2*)&wr_s[c*64 + 2*og];
        float2 wi = *(const float2*)&wi_s[c*64 + 2*og];
        re = ffma2(dup2(xr),  wr, re);
        re = ffma2(dup2(-xi), wi, re);
        im = ffma2(dup2(xr),  wi, im);
        im = ffma2(dup2(xi),  wr, im);
    }
    int base = (m*Bn + b)*Cn + 2*og;
    *(float2*)&g_oft_re[base] = re;
    *(float2*)&g_oft_im[base] = im;
}

// ---------------- K4: inverse DFT over H (ffma2 on ar/ai) -----------------
__global__ void __launch_bounds__(128) k4_idftH() {
    __shared__ float osm[576*2];
    __shared__ float cs[24*128], sn[24*128];
    int bx = blockIdx.x;
    int b = bx >> 6, o = bx & 63;
    int tid = threadIdx.x;
    for (int i = tid; i < 576; i += 128) {
        osm[2*i]   = g_oft_re[i*1024 + b*64 + o];
        osm[2*i+1] = g_oft_im[i*1024 + b*64 + o];
    }
    for (int i = tid; i < 3072; i += 128) { cs[i] = g_cos[i]; sn[i] = g_sin[i]; }
    __syncthreads();

    int h = tid;
    float2 acc[24];
    #pragma unroll
    for (int ky = 0; ky < 24; ky++) acc[ky] = make_float2(0.f, 0.f);
    #pragma unroll 2
    for (int kx = 0; kx < 24; kx++) {
        float cr = cs[kx*128 + h];
        float si = sn[kx*128 + h];
        float2 v1 = make_float2(cr, si);
        float2 v2 = make_float2(-si, cr);
        #pragma unroll
        for (int ky = 0; ky < 24; ky++) {
            float2 ov = *(const float2*)&osm[(kx*24 + ky)*2];
            acc[ky] = ffma2(dup2(ov.x), v1, acc[ky]);
            acc[ky] = ffma2(dup2(ov.y), v2, acc[ky]);
        }
    }
    size_t base = (((size_t)b*128 + h)*64 + o)*24;
    const float sc = 1.0f/16384.0f;
    #pragma unroll
    for (int ky = 0; ky < 24; ky++) {
        float s = (ky == 0) ? sc : 2.0f*sc;
        g_S_re[base + ky] = acc[ky].x*s;
        g_S_im[base + ky] = acc[ky].y*s;
    }
}

// ---------------- K5: fused final via mma.sync tf32 -----------------------
// smem layout (floats):
//   xs   [2][64][136]  17408   (rows reused as zs: zs[hr] = xs + hr*4352, [32][136])
//   h1s  [2][64][136]  17408   (reused as output staging after phase3)
//   wskA [64][72]       4608   (k-permuted tf32)
//   SrA  [2][64][28]    3584   (tf32)
//   SiA  [2][64][28]    3584   (tf32, negated)
//   trig [48][136]      6528   (rows 0-23 cos, 24-47 sin; tf32)
//   f1A  [32][72]       2304   (k-permuted tf32)
//   f2A  [64][36]       2304   (k-permuted tf32)
//   b1s 32, b2s 64, gs 64
#define K5_SMEM_FLOATS 57888
#define SX 136

__global__ void __launch_bounds__(512, 1) k5_final(
    const float* __restrict__ x,
    const float* __restrict__ wsk_g,
    const float* __restrict__ f1w_g, const float* __restrict__ f1b_g,
    const float* __restrict__ f2w_g, const float* __restrict__ f2b_g,
    const float* __restrict__ gate_g,
    float* __restrict__ out)
{
    extern __shared__ float sm[];
    float* xs   = sm;
    float* h1s  = sm + 17408;
    float* wskA = sm + 34816;
    float* SrA  = sm + 39424;
    float* SiA  = sm + 43008;
    float* trig = sm + 46592;
    float* f1A  = sm + 53120;
    float* f2A  = sm + 55424;
    float* b1s  = sm + 57728;
    float* b2s  = sm + 57760;
    float* gs   = sm + 57824;

    int tid  = threadIdx.x;
    int lane = tid & 31;
    int wid  = tid >> 5;          // 0..15
    int hr   = wid >> 3;          // row within block
    int w8   = wid & 7;
    int p    = w8 & 1;            // m-pair (rows 32p..32p+31)
    int q    = w8 >> 1;           // n-quad (cols 32q..32q+31)
    int qr   = lane >> 2;         // 0..7
    int qc   = lane & 3;          // 0..3
    int hb = blockIdx.x;          // rows 2*hb, 2*hb+1
    int b  = blockIdx.y;

    // ---- cooperative loads (all tf32-converted) ----
    for (int i = tid; i < 4096; i += 512) {
        int hh = i >> 11, c = (i >> 5) & 63, w = (i & 31) * 4;
        float4 v = *(const float4*)&x[(((size_t)b*64 + c)*128 + (2*hb + hh))*128 + w];
        v.x = tf32f(v.x); v.y = tf32f(v.y); v.z = tf32f(v.z); v.w = tf32f(v.w);
        *(float4*)&xs[hh*8704 + c*SX + w] = v;
    }
    for (int i = tid; i < 6144; i += 512) {
        int r = i >> 7, w = i & 127;
        float v = (r < 24) ? g_cos[r*128 + w] : g_sin[(r-24)*128 + w];
        trig[r*SX + w] = tf32f(v);
    }
    for (int i = tid; i < 4096; i += 512) {
        int o = i >> 6, c = i & 63;
        int cp = (c & ~7) + ((c & 3) << 1) + ((c >> 2) & 1);
        wskA[o*72 + cp] = tf32f(wsk_g[i]);
    }
    {
        size_t sb = ((size_t)b*128 + 2*hb) * (64*24);
        for (int i = tid; i < 3072; i += 512) {
            int hh = i / 1536, j = i - hh*1536;
            int o = j / 24, ky = j - o*24;
            SrA[hh*1792 + o*28 + ky] = tf32f( g_S_re[sb + (size_t)hh*1536 + j]);
            SiA[hh*1792 + o*28 + ky] = tf32f(-g_S_im[sb + (size_t)hh*1536 + j]);
        }
    }
    for (int i = tid; i < 2048; i += 512) {
        int k = i >> 6, c = i & 63;
        int cp = (c & ~7) + ((c & 3) << 1) + ((c >> 2) & 1);
        f1A[k*72 + cp] = tf32f(f1w_g[i]);
    }
    for (int i = tid; i < 2048; i += 512) {
        int o = i >> 5, k = i & 31;
        int kp = (k & ~7) + ((k & 3) << 1) + ((k >> 2) & 1);
        f2A[o*36 + kp] = tf32f(f2w_g[i]);
    }
    if (tid < 32) b1s[tid] = f1b_g[tid];
    if (tid < 64) { b2s[tid] = f2b_g[tid]; gs[tid] = gate_g[tid]; }
    __syncthreads();

    const float* xrow  = xs  + hr*8704;
    const float* h1row = h1s + hr*8704;

    // ================= phase 1+2: skip GEMM + spectral GEMM =================
    float d1[2][4][4];
    #pragma unroll
    for (int t = 0; t < 2; t++)
        #pragma unroll
        for (int j = 0; j < 4; j++)
            #pragma unroll
            for (int e = 0; e < 4; e++) d1[t][j][e] = 0.f;

    // skip: K = 64 over channels
    #pragma unroll
    for (int ks = 0; ks < 8; ks++) {
        int k0 = ks * 8;
        uint32_t a[2][4];
        #pragma unroll
        for (int t = 0; t < 2; t++) {
            int R = 32*p + 16*t;
            float2 lo = *(const float2*)&wskA[(R+qr)*72 + k0 + 2*qc];
            float2 hi = *(const float2*)&wskA[(R+qr+8)*72 + k0 + 2*qc];
            a[t][0] = fbits(lo.x); a[t][1] = fbits(hi.x);
            a[t][2] = fbits(lo.y); a[t][3] = fbits(hi.y);
        }
        #pragma unroll
        for (int j = 0; j < 4; j++) {
            int N = 32*q + 8*j;
            uint32_t b0 = fbits(xrow[(k0+qc)*SX + N + qr]);
            uint32_t b1 = fbits(xrow[(k0+qc+4)*SX + N + qr]);
            mma8(d1[0][j], a[0][0], a[0][1], a[0][2], a[0][3], b0, b1);
            mma8(d1[1][j], a[1][0], a[1][1], a[1][2], a[1][3], b0, b1);
        }
    }
    // spectral: K = 24 (cos) + 24 (sin, A pre-negated)
    const float* Sr_ = SrA + hr*1792;
    const float* Si_ = SiA + hr*1792;
    #pragma unroll
    for (int ks = 0; ks < 3; ks++) {
        int k0 = ks * 8;
        uint32_t ar[2][4], ai[2][4];
        #pragma unroll
        for (int t = 0; t < 2; t++) {
            int R = 32*p + 16*t;
            ar[t][0] = fbits(Sr_[(R+qr)*28   + k0 + qc]);
            ar[t][1] = fbits(Sr_[(R+qr+8)*28 + k0 + qc]);
            ar[t][2] = fbits(Sr_[(R+qr)*28   + k0 + qc + 4]);
            ar[t][3] = fbits(Sr_[(R+qr+8)*28 + k0 + qc + 4]);
            ai[t][0] = fbits(Si_[(R+qr)*28   + k0 + qc]);
            ai[t][1] = fbits(Si_[(R+qr+8)*28 + k0 + qc]);
            ai[t][2] = fbits(Si_[(R+qr)*28   + k0 + qc + 4]);
            ai[t][3] = fbits(Si_[(R+qr+8)*28 + k0 + qc + 4]);
        }
        #pragma unroll
        for (int j = 0; j < 4; j++) {
            int N = 32*q + 8*j;
            uint32_t c0 = fbits(trig[(k0+qc)*SX      + N + qr]);
            uint32_t c1 = fbits(trig[(k0+qc+4)*SX    + N + qr]);
            uint32_t s0 = fbits(trig[(24+k0+qc)*SX   + N + qr]);
            uint32_t s1 = fbits(trig[(24+k0+qc+4)*SX + N + qr]);
            mma8(d1[0][j], ar[0][0], ar[0][1], ar[0][2], ar[0][3], c0, c1);
            mma8(d1[1][j], ar[1][0], ar[1][1], ar[1][2], ar[1][3], c0, c1);
            mma8(d1[0][j], ai[0][0], ai[0][1], ai[0][2], ai[0][3], s0, s1);
            mma8(d1[1][j], ai[1][0], ai[1][1], ai[1][2], ai[1][3], s0, s1);
        }
    }

    // gelu -> h1 (fp32 kept in regs for gate; tf32 copy to smem)
    float h1r[2][4][4];
    #pragma unroll
    for (int t = 0; t < 2; t++) {
        int row0 = 32*p + 16*t + qr;
        #pragma unroll
        for (int j = 0; j < 4; j++) {
            int N = 32*q + 8*j;
            #pragma unroll
            for (int e = 0; e < 4; e++) h1r[t][j][e] = gelu_f(d1[t][j][e]);
            *(float2*)&h1s[hr*8704 + row0*SX + N + 2*qc] =
                make_float2(tf32f(h1r[t][j][0]), tf32f(h1r[t][j][1]));
            *(float2*)&h1s[hr*8704 + (row0+8)*SX + N + 2*qc] =
                make_float2(tf32f(h1r[t][j][2]), tf32f(h1r[t][j][3]));
        }
    }
    __syncthreads();

    // ================= phase 3: fc1 + gelu -> zs ============================
    float d3[2][2][4];
    #pragma unroll
    for (int t = 0; t < 2; t++)
        #pragma unroll
        for (int j = 0; j < 2; j++)
            #pragma unroll
            for (int e = 0; e < 4; e++) d3[t][j][e] = 0.f;

    #pragma unroll
    for (int ks = 0; ks < 8; ks++) {
        int k0 = ks * 8;
        uint32_t a[2][4];
        #pragma unroll
        for (int t = 0; t < 2; t++) {
            int R = 16*t;
            float2 lo = *(const float2*)&f1A[(R+qr)*72 + k0 + 2*qc];
            float2 hi = *(const float2*)&f1A[(R+qr+8)*72 + k0 + 2*qc];
            a[t][0] = fbits(lo.x); a[t][1] = fbits(hi.x);
            a[t][2] = fbits(lo.y); a[t][3] = fbits(hi.y);
        }
        #pragma unroll
        for (int j = 0; j < 2; j++) {
            int N3 = 16*w8 + 8*j;
            uint32_t b0 = fbits(h1row[(k0+qc)*SX + N3 + qr]);
            uint32_t b1 = fbits(h1row[(k0+qc+4)*SX + N3 + qr]);
            mma8(d3[0][j], a[0][0], a[0][1], a[0][2], a[0][3], b0, b1);
            mma8(d3[1][j], a[1][0], a[1][1], a[1][2], a[1][3], b0, b1);
        }
    }
    float* zrow = xs + hr*4352;   // alias: xs dead after phase1 reads
    #pragma unroll
    for (int t = 0; t < 2; t++) {
        int row0 = 16*t + qr;
        float bb0 = b1s[row0], bb8 = b1s[row0+8];
        #pragma unroll
        for (int j = 0; j < 2; j++) {
            int N3 = 16*w8 + 8*j;
            *(float2*)&zrow[row0*SX + N3 + 2*qc] =
                make_float2(tf32f(gelu_f(d3[t][j][0] + bb0)),
                            tf32f(gelu_f(d3[t][j][1] + bb0)));
            *(float2*)&zrow[(row0+8)*SX + N3 + 2*qc] =
                make_float2(tf32f(gelu_f(d3[t][j][2] + bb8)),
                            tf32f(gelu_f(d3[t][j][3] + bb8)));
        }
    }
    __syncthreads();

    // ================= phase 4: fc2 + bias + gate*h1 ========================
    float d4[2][4][4];
    #pragma unroll
    for (int t = 0; t < 2; t++) {
        int row0 = 32*p + 16*t + qr;
        float bb0 = b2s[row0], bb8 = b2s[row0+8];
        #pragma unroll
        for (int j = 0; j < 4; j++) {
            d4[t][j][0] = bb0; d4[t][j][1] = bb0;
            d4[t][j][2] = bb8; d4[t][j][3] = bb8;
        }
    }
    #pragma unroll
    for (int ks = 0; ks < 4; ks++) {
        int k0 = ks * 8;
        uint32_t a[2][4];
        #pragma unroll
        for (int t = 0; t < 2; t++) {
            int R = 32*p + 16*t;
            float2 lo = *(const float2*)&f2A[(R+qr)*36 + k0 + 2*qc];
            float2 hi = *(const float2*)&f2A[(R+qr+8)*36 + k0 + 2*qc];
            a[t][0] = fbits(lo.x); a[t][1] = fbits(hi.x);
            a[t][2] = fbits(lo.y); a[t][3] = fbits(hi.y);
        }
        #pragma unroll
        for (int j = 0; j < 4; j++) {
            int N = 32*q + 8*j;
            uint32_t b0 = fbits(zrow[(k0+qc)*SX + N + qr]);
            uint32_t b1 = fbits(zrow[(k0+qc+4)*SX + N + qr]);
            mma8(d4[0][j], a[0][0], a[0][1], a[0][2], a[0][3], b0, b1);
            mma8(d4[1][j], a[1][0], a[1][1], a[1][2], a[1][3], b0, b1);
        }
    }
    // gate add, stage into h1s (free after phase3 reads)
    #pragma unroll
    for (int t = 0; t < 2; t++) {
        int row0 = 32*p + 16*t + qr;
        float g0 = gs[row0], g8 = gs[row0+8];
        #pragma unroll
        for (int j = 0; j < 4; j++) {
            int N = 32*q + 8*j;
            *(float2*)&h1s[hr*8704 + row0*SX + N + 2*qc] =
                make_float2(d4[t][j][0] + g0*h1r[t][j][0],
                            d4[t][j][1] + g0*h1r[t][j][1]);
            *(float2*)&h1s[hr*8704 + (row0+8)*SX + N + 2*qc] =
                make_float2(d4[t][j][2] + g8*h1r[t][j][2],
                            d4[t][j][3] + g8*h1r[t][j][3]);
        }
    }
    __syncthreads();

    // coalesced final store
    for (int i = tid; i < 4096; i += 512) {
        int hh = i >> 11, c = (i >> 5) & 63, w = (i & 31) * 4;
        float4 v = *(const float4*)&h1s[hh*8704 + c*SX + w];
        *(float4*)&out[(((size_t)b*64 + c)*128 + (2*hb + hh))*128 + w] = v;
    }
}

// ---------------- launch ----------------
extern "C" void kernel_launch(void* const* d_in, const int* in_sizes, int n_in,
                              void* d_out, int out_size) {
    const float* x    = (const float*)d_in[0];
    const float* wre  = (const float*)d_in[1];
    const float* wim  = (const float*)d_in[2];
    const float* wsk  = (const float*)d_in[3];
    const float* f1w  = (const float*)d_in[4];
    const float* f1b  = (const float*)d_in[5];
    const float* f2w  = (const float*)d_in[6];
    const float* f2b  = (const float*)d_in[7];
    const float* gate = (const float*)d_in[8];
    float* out = (float*)d_out;

    cudaFuncSetAttribute(k5_final, cudaFuncAttributeMaxDynamicSharedMemorySize,
                         K5_SMEM_FLOATS * (int)sizeof(float));

    k0_init<<<6, 512>>>();
    k1_dftW<<<1024, 384>>>(x);
    k2_dftH<<<1024, 288>>>();
    k3_mix<<<576, 512>>>(wre, wim);
    k4_idftH<<<1024, 128>>>();
    dim3 g5(64, 16);
    k5_final<<<g5, 512, K5_SMEM_FLOATS * sizeof(float)>>>(
        x, wsk, f1w, f1b, f2w, f2b, gate, out);
}

// round 6
// speedup vs baseline: 1.0009x; 1.0009x over previous
#include <cuda_runtime.h>
#include <math.h>
#include <stdint.h>

#define Bn 16
#define Cn 64
#define Hn 128
#define Wn 128
#define MXn 24
#define MYn 24
#define HIDn 32

// ---------------- scratch (device globals; no runtime allocation) ----------
__device__ float g_xw_re[Bn*Cn*Hn*MYn];       // [b][c][h][ky]
__device__ float g_xw_im[Bn*Cn*Hn*MYn];
__device__ float g_xft_re[MXn*MYn*Bn*Cn];     // [(kx*24+ky)][b][c]
__device__ float g_xft_im[MXn*MYn*Bn*Cn];
__device__ float g_oft_re[MXn*MYn*Bn*Cn];     // [(kx*24+ky)][b][o]
__device__ float g_oft_im[MXn*MYn*Bn*Cn];
__device__ float g_S_re[Bn*Hn*Cn*MYn];        // [b][h][o][ky]  (scaled)
__device__ float g_S_im[Bn*Hn*Cn*MYn];
__device__ float g_cos[MYn*Wn];               // cos(2*pi*k*w/128)
__device__ float g_sin[MYn*Wn];               // sin(2*pi*k*w/128)
__device__ float g_twT[Wn*48];                // [w][j] j<24: cos, j>=24: -sin

// ---------------- packed f32x2 helpers ----------------
__device__ __forceinline__ float2 ffma2(float2 a, float2 b, float2 c) {
    float2 r;
    asm("fma.rn.f32x2 %0, %1, %2, %3;"
        : "=l"(reinterpret_cast<unsigned long long&>(r))
        : "l"(reinterpret_cast<unsigned long long&>(a)),
          "l"(reinterpret_cast<unsigned long long&>(b)),
          "l"(reinterpret_cast<unsigned long long&>(c)));
    return r;
}
__device__ __forceinline__ float2 dup2(float x) { return make_float2(x, x); }

__device__ __forceinline__ float gelu_f(float v) {
    return 0.5f*v*(1.0f + erff(v*0.7071067811865476f));
}

// tf32 helpers
__device__ __forceinline__ float tf32f(float x) {
    uint32_t u;
    asm("cvt.rna.tf32.f32 %0, %1;" : "=r"(u) : "f"(x));
    return __uint_as_float(u);
}
__device__ __forceinline__ uint32_t fbits(float x) { return __float_as_uint(x); }

// mma.sync m16n8k8 tf32: D += A*B (D,C fp32)
__device__ __forceinline__ void mma8(float* d,
                                     uint32_t a0, uint32_t a1, uint32_t a2, uint32_t a3,
                                     uint32_t b0, uint32_t b1) {
    asm volatile(
        "mma.sync.aligned.m16n8k8.row.col.f32.tf32.tf32.f32 "
        "{%0,%1,%2,%3},{%4,%5,%6,%7},{%8,%9},{%0,%1,%2,%3};"
        : "+f"(d[0]), "+f"(d[1]), "+f"(d[2]), "+f"(d[3])
        : "r"(a0), "r"(a1), "r"(a2), "r"(a3), "r"(b0), "r"(b1));
}

// ---------------- K0: twiddle init ----------------
__global__ void k0_init() {
    int i = blockIdx.x*blockDim.x + threadIdx.x;
    if (i >= MYn*Wn) return;
    int k = i / Wn, w = i % Wn;
    float s, c;
    sincospif((float)(k*w) / 64.0f, &s, &c);
    g_cos[k*Wn + w] = c;
    g_sin[k*Wn + w] = s;
    g_twT[w*48 + k]      = c;
    g_twT[w*48 + 24 + k] = -s;
}

// ---------------- K1: partial DFT over W (ffma2 on row pairs) -------------
__global__ void __launch_bounds__(384) k1_dftW(const float* __restrict__ x) {
    __shared__ float Xs[32*132];
    __shared__ float Tw[32*48];
    int tid = threadIdx.x;
    int rg = tid & 31;
    int jg = tid >> 5;
    int row0 = blockIdx.x * 128;

    float2 acc[2][4];
    #pragma unroll
    for (int i = 0; i < 2; i++)
        #pragma unroll
        for (int j = 0; j < 4; j++) acc[i][j] = make_float2(0.f, 0.f);

    for (int kt = 0; kt < 4; kt++) {
        for (int i = tid; i < 4096; i += 384) {
            int r = i >> 5, w = i & 31;
            Xs[w*132 + r] = x[(size_t)(row0 + r)*128 + kt*32 + w];
        }
        for (int i = tid; i < 32*48; i += 384)
            Tw[i] = g_twT[kt*32*48 + i];
        __syncthreads();
        #pragma unroll
        for (int kk = 0; kk < 32; kk++) {
            float4 xa = *(const float4*)&Xs[kk*132 + 4*rg];
            float2 xp0 = make_float2(xa.x, xa.y);
            float2 xp1 = make_float2(xa.z, xa.w);
            float4 tq = *(const float4*)&Tw[kk*48 + 4*jg];
            float tv[4] = { tq.x, tq.y, tq.z, tq.w };
            #pragma unroll
            for (int j = 0; j < 4; j++) {
                float2 td = dup2(tv[j]);
                acc[0][j] = ffma2(xp0, td, acc[0][j]);
                acc[1][j] = ffma2(xp1, td, acc[1][j]);
            }
        }
        __syncthreads();
    }

    float* dst = (jg < 6) ? g_xw_re : g_xw_im;
    int col = (jg < 6) ? (4*jg) : (4*jg - 24);
    #pragma unroll
    for (int i = 0; i < 4; i++) {
        int pair = i >> 1, half = i & 1;
        float v0 = half ? acc[pair][0].y : acc[pair][0].x;
        float v1 = half ? acc[pair][1].y : acc[pair][1].x;
        float v2 = half ? acc[pair][2].y : acc[pair][2].x;
        float v3 = half ? acc[pair][3].y : acc[pair][3].x;
        int r = row0 + 4*rg + i;
        *(float4*)&dst[(size_t)r*24 + col] = make_float4(v0, v1, v2, v3);
    }
}

// ---------------- K2: partial DFT over H (ffma2 on re/im) -----------------
__global__ void __launch_bounds__(288) k2_dftH() {
    __shared__ float xr[128*24], xi[128*24];
    __shared__ float cs[24*128], sn[24*128];
    int bc = blockIdx.x;
    int tid = threadIdx.x;
    size_t base = (size_t)bc * (128*24);
    for (int i = tid; i < 3072; i += 288) {
        xr[i] = g_xw_re[base + i];
        xi[i] = g_xw_im[base + i];
        cs[i] = g_cos[i];
        sn[i] = g_sin[i];
    }
    __syncthreads();

    int ky  = tid % 24;
    int kxg = tid / 24;
    int kx0 = 2*kxg, kx1 = 2*kxg + 1;
    float2 acc0 = make_float2(0.f, 0.f);
    float2 acc1 = make_float2(0.f, 0.f);
    #pragma unroll 4
    for (int h = 0; h < 128; h++) {
        float a = xr[h*24 + ky];
        float b = xi[h*24 + ky];
        float2 ab  = make_float2(a, b);
        float2 bna = make_float2(b, -a);
        acc0 = ffma2(ab,  dup2(cs[kx0*128 + h]), acc0);
        acc0 = ffma2(bna, dup2(sn[kx0*128 + h]), acc0);
        acc1 = ffma2(ab,  dup2(cs[kx1*128 + h]), acc1);
        acc1 = ffma2(bna, dup2(sn[kx1*128 + h]), acc1);
    }
    int b = bc >> 6, c = bc & 63;
    int m0 = kx0*24 + ky, m1 = kx1*24 + ky;
    g_xft_re[(m0*Bn + b)*Cn + c] = acc0.x;
    g_xft_im[(m0*Bn + b)*Cn + c] = acc0.y;
    g_xft_re[(m1*Bn + b)*Cn + c] = acc1.x;
    g_xft_im[(m1*Bn + b)*Cn + c] = acc1.y;
}

// ---------------- K3: per-mode complex channel mix (512 thr) --------------
__global__ void __launch_bounds__(512) k3_mix(const float* __restrict__ wr_g,
                                              const float* __restrict__ wi_g) {
    __shared__ float xr_s[1024], xi_s[1024];
    __shared__ float wr_s[4096], wi_s[4096];
    int m = blockIdx.x, tid = threadIdx.x;
    for (int i = tid; i < 1024; i += 512) {
        xr_s[i] = g_xft_re[m*1024 + i];
        xi_s[i] = g_xft_im[m*1024 + i];
    }
    for (int i = tid; i < 4096; i += 512) {
        wr_s[i] = wr_g[(size_t)m*4096 + i];
        wi_s[i] = wi_g[(size_t)m*4096 + i];
    }
    __syncthreads();

    int b  = tid >> 5;
    int og = tid & 31;
    float2 re = make_float2(0.f, 0.f), im = make_float2(0.f, 0.f);
    #pragma unroll 4
    for (int c = 0; c < 64; c++) {
        float xr = xr_s[b*64 + c];
        float xi = xi_s[b*64 + c];
        float2 wr = *(const float2*)&wr_s[c*64 + 2*og];
        float2 wi = *(const float2*)&wi_s[c*64 + 2*og];
        re = ffma2(dup2(xr),  wr, re);
        re = ffma2(dup2(-xi), wi, re);
        im = ffma2(dup2(xr),  wi, im);
        im = ffma2(dup2(xi),  wr, im);
    }
    int base = (m*Bn + b)*Cn + 2*og;
    *(float2*)&g_oft_re[base] = re;
    *(float2*)&g_oft_im[base] = im;
}

// ---------------- K4: inverse DFT over H (ffma2 on ar/ai) -----------------
__global__ void __launch_bounds__(128) k4_idftH() {
    __shared__ float osm[576*2];
    __shared__ float cs[24*128], sn[24*128];
    int bx = blockIdx.x;
    int b = bx >> 6, o = bx & 63;
    int tid = threadIdx.x;
    for (int i = tid; i < 576; i += 128) {
        osm[2*i]   = g_oft_re[i*1024 + b*64 + o];
        osm[2*i+1] = g_oft_im[i*1024 + b*64 + o];
    }
    for (int i = tid; i < 3072; i += 128) { cs[i] = g_cos[i]; sn[i] = g_sin[i]; }
    __syncthreads();

    int h = tid;
    float2 acc[24];
    #pragma unroll
    for (int ky = 0; ky < 24; ky++) acc[ky] = make_float2(0.f, 0.f);
    #pragma unroll 2
    for (int kx = 0; kx < 24; kx++) {
        float cr = cs[kx*128 + h];
        float si = sn[kx*128 + h];
        float2 v1 = make_float2(cr, si);
        float2 v2 = make_float2(-si, cr);
        #pragma unroll
        for (int ky = 0; ky < 24; ky++) {
            float2 ov = *(const float2*)&osm[(kx*24 + ky)*2];
            acc[ky] = ffma2(dup2(ov.x), v1, acc[ky]);
            acc[ky] = ffma2(dup2(ov.y), v2, acc[ky]);
        }
    }
    size_t base = (((size_t)b*128 + h)*64 + o)*24;
    const float sc = 1.0f/16384.0f;
    #pragma unroll
    for (int ky = 0; ky < 24; ky++) {
        float s = (ky == 0) ? sc : 2.0f*sc;
        g_S_re[base + ky] = acc[ky].x*s;
        g_S_im[base + ky] = acc[ky].y*s;
    }
}

// ---------------- K5: fused final via mma.sync tf32 -----------------------
// smem layout (floats):
//   xs   [2][64][136]  17408   (rows reused as zs: zs[hr] = xs + hr*4352, [32][136])
//   h1s  [2][64][136]  17408   (reused as output staging after phase3)
//   wskA [64][72]       4608   (k-permuted tf32)
//   SrA  [2][64][28]    3584   (tf32)
//   SiA  [2][64][28]    3584   (tf32, negated)
//   trig [48][136]      6528   (rows 0-23 cos, 24-47 sin; tf32)
//   f1A  [32][72]       2304   (k-permuted tf32)
//   f2A  [64][36]       2304   (k-permuted tf32)
//   b1s 32, b2s 64, gs 64
#define K5_SMEM_FLOATS 57888
#define SX 136

__global__ void __launch_bounds__(512, 1) k5_final(
    const float* __restrict__ x,
    const float* __restrict__ wsk_g,
    const float* __restrict__ f1w_g, const float* __restrict__ f1b_g,
    const float* __restrict__ f2w_g, const float* __restrict__ f2b_g,
    const float* __restrict__ gate_g,
    float* __restrict__ out)
{
    extern __shared__ float sm[];
    float* xs   = sm;
    float* h1s  = sm + 17408;
    float* wskA = sm + 34816;
    float* SrA  = sm + 39424;
    float* SiA  = sm + 43008;
    float* trig = sm + 46592;
    float* f1A  = sm + 53120;
    float* f2A  = sm + 55424;
    float* b1s  = sm + 57728;
    float* b2s  = sm + 57760;
    float* gs   = sm + 57824;

    int tid  = threadIdx.x;
    int lane = tid & 31;
    int wid  = tid >> 5;          // 0..15
    int hr   = wid >> 3;          // row within block
    int w8   = wid & 7;
    int p    = w8 & 1;            // m-pair (rows 32p..32p+31)
    int q    = w8 >> 1;           // n-quad (cols 32q..32q+31)
    int qr   = lane >> 2;         // 0..7
    int qc   = lane & 3;          // 0..3
    int hb = blockIdx.x;          // rows 2*hb, 2*hb+1
    int b  = blockIdx.y;

    // ---- cooperative loads (all tf32-converted) ----
    for (int i = tid; i < 4096; i += 512) {
        int hh = i >> 11, c = (i >> 5) & 63, w = (i & 31) * 4;
        float4 v = *(const float4*)&x[(((size_t)b*64 + c)*128 + (2*hb + hh))*128 + w];
        v.x = tf32f(v.x); v.y = tf32f(v.y); v.z = tf32f(v.z); v.w = tf32f(v.w);
        *(float4*)&xs[hh*8704 + c*SX + w] = v;
    }
    for (int i = tid; i < 6144; i += 512) {
        int r = i >> 7, w = i & 127;
        float v = (r < 24) ? g_cos[r*128 + w] : g_sin[(r-24)*128 + w];
        trig[r*SX + w] = tf32f(v);
    }
    for (int i = tid; i < 4096; i += 512) {
        int o = i >> 6, c = i & 63;
        int cp = (c & ~7) + ((c & 3) << 1) + ((c >> 2) & 1);
        wskA[o*72 + cp] = tf32f(wsk_g[i]);
    }
    {
        size_t sb = ((size_t)b*128 + 2*hb) * (64*24);
        for (int i = tid; i < 3072; i += 512) {
            int hh = i / 1536, j = i - hh*1536;
            int o = j / 24, ky = j - o*24;
            SrA[hh*1792 + o*28 + ky] = tf32f( g_S_re[sb + (size_t)hh*1536 + j]);
            SiA[hh*1792 + o*28 + ky] = tf32f(-g_S_im[sb + (size_t)hh*1536 + j]);
        }
    }
    for (int i = tid; i < 2048; i += 512) {
        int k = i >> 6, c = i & 63;
        int cp = (c & ~7) + ((c & 3) << 1) + ((c >> 2) & 1);
        f1A[k*72 + cp] = tf32f(f1w_g[i]);
    }
    for (int i = tid; i < 2048; i += 512) {
        int o = i >> 5, k = i & 31;
        int kp = (k & ~7) + ((k & 3) << 1) + ((k >> 2) & 1);
        f2A[o*36 + kp] = tf32f(f2w_g[i]);
    }
    if (tid < 32) b1s[tid] = f1b_g[tid];
    if (tid < 64) { b2s[tid] = f2b_g[tid]; gs[tid] = gate_g[tid]; }
    __syncthreads();

    const float* xrow  = xs  + hr*8704;
    const float* h1row = h1s + hr*8704;

    // ================= phase 1+2: skip GEMM + spectral GEMM =================
    float d1[2][4][4];
    #pragma unroll
    for (int t = 0; t < 2; t++)
        #pragma unroll
        for (int j = 0; j < 4; j++)
            #pragma unroll
            for (int e = 0; e < 4; e++) d1[t][j][e] = 0.f;

    // skip: K = 64 over channels
    #pragma unroll
    for (int ks = 0; ks < 8; ks++) {
        int k0 = ks * 8;
        uint32_t a[2][4];
        #pragma unroll
        for (int t = 0; t < 2; t++) {
            int R = 32*p + 16*t;
            float2 lo = *(const float2*)&wskA[(R+qr)*72 + k0 + 2*qc];
            float2 hi = *(const float2*)&wskA[(R+qr+8)*72 + k0 + 2*qc];
            a[t][0] = fbits(lo.x); a[t][1] = fbits(hi.x);
            a[t][2] = fbits(lo.y); a[t][3] = fbits(hi.y);
        }
        #pragma unroll
        for (int j = 0; j < 4; j++) {
            int N = 32*q + 8*j;
            uint32_t b0 = fbits(xrow[(k0+qc)*SX + N + qr]);
            uint32_t b1 = fbits(xrow[(k0+qc+4)*SX + N + qr]);
            mma8(d1[0][j], a[0][0], a[0][1], a[0][2], a[0][3], b0, b1);
            mma8(d1[1][j], a[1][0], a[1][1], a[1][2], a[1][3], b0, b1);
        }
    }
    // spectral: K = 24 (cos) + 24 (sin, A pre-negated)
    const float* Sr_ = SrA + hr*1792;
    const float* Si_ = SiA + hr*1792;
    #pragma unroll
    for (int ks = 0; ks < 3; ks++) {
        int k0 = ks * 8;
        uint32_t ar[2][4], ai[2][4];
        #pragma unroll
        for (int t = 0; t < 2; t++) {
            int R = 32*p + 16*t;
            ar[t][0] = fbits(Sr_[(R+qr)*28   + k0 + qc]);
            ar[t][1] = fbits(Sr_[(R+qr+8)*28 + k0 + qc]);
            ar[t][2] = fbits(Sr_[(R+qr)*28   + k0 + qc + 4]);
            ar[t][3] = fbits(Sr_[(R+qr+8)*28 + k0 + qc + 4]);
            ai[t][0] = fbits(Si_[(R+qr)*28   + k0 + qc]);
            ai[t][1] = fbits(Si_[(R+qr+8)*28 + k0 + qc]);
            ai[t][2] = fbits(Si_[(R+qr)*28   + k0 + qc + 4]);
            ai[t][3] = fbits(Si_[(R+qr+8)*28 + k0 + qc + 4]);
        }
        #pragma unroll
        for (int j = 0; j < 4; j++) {
            int N = 32*q + 8*j;
            uint32_t c0 = fbits(trig[(k0+qc)*SX      + N + qr]);
            uint32_t c1 = fbits(trig[(k0+qc+4)*SX    + N + qr]);
            uint32_t s0 = fbits(trig[(24+k0+qc)*SX   + N + qr]);
            uint32_t s1 = fbits(trig[(24+k0+qc+4)*SX + N + qr]);
            mma8(d1[0][j], ar[0][0], ar[0][1], ar[0][2], ar[0][3], c0, c1);
            mma8(d1[1][j], ar[1][0], ar[1][1], ar[1][2], ar[1][3], c0, c1);
            mma8(d1[0][j], ai[0][0], ai[0][1], ai[0][2], ai[0][3], s0, s1);
            mma8(d1[1][j], ai[1][0], ai[1][1], ai[1][2], ai[1][3], s0, s1);
        }
    }

    // gelu -> h1 (fp32 kept in regs for gate; tf32 copy to smem)
    float h1r[2][4][4];
    #pragma unroll
    for (int t = 0; t < 2; t++) {
        int row0 = 32*p + 16*t + qr;
        #pragma unroll
        for (int j = 0; j < 4; j++) {
            int N = 32*q + 8*j;
            #pragma unroll
            for (int e = 0; e < 4; e++) h1r[t][j][e] = gelu_f(d1[t][j][e]);
            *(float2*)&h1s[hr*8704 + row0*SX + N + 2*qc] =
                make_float2(tf32f(h1r[t][j][0]), tf32f(h1r[t][j][1]));
            *(float2*)&h1s[hr*8704 + (row0+8)*SX + N + 2*qc] =
                make_float2(tf32f(h1r[t][j][2]), tf32f(h1r[t][j][3]));
        }
    }
    __syncthreads();

    // ================= phase 3: fc1 + gelu -> zs ============================
    float d3[2][2][4];
    #pragma unroll
    for (int t = 0; t < 2; t++)
        #pragma unroll
        for (int j = 0; j < 2; j++)
            #pragma unroll
            for (int e = 0; e < 4; e++) d3[t][j][e] = 0.f;

    #pragma unroll
    for (int ks = 0; ks < 8; ks++) {
        int k0 = ks * 8;
        uint32_t a[2][4];
        #pragma unroll
        for (int t = 0; t < 2; t++) {
            int R = 16*t;
            float2 lo = *(const float2*)&f1A[(R+qr)*72 + k0 + 2*qc];
            float2 hi = *(const float2*)&f1A[(R+qr+8)*72 + k0 + 2*qc];
            a[t][0] = fbits(lo.x); a[t][1] = fbits(hi.x);
            a[t][2] = fbits(lo.y); a[t][3] = fbits(hi.y);
        }
        #pragma unroll
        for (int j = 0; j < 2; j++) {
            int N3 = 16*w8 + 8*j;
            uint32_t b0 = fbits(h1row[(k0+qc)*SX + N3 + qr]);
            uint32_t b1 = fbits(h1row[(k0+qc+4)*SX + N3 + qr]);
            mma8(d3[0][j], a[0][0], a[0][1], a[0][2], a[0][3], b0, b1);
            mma8(d3[1][j], a[1][0], a[1][1], a[1][2], a[1][3], b0, b1);
        }
    }
    float* zrow = xs + hr*4352;   // alias: xs dead after phase1 reads
    #pragma unroll
    for (int t = 0; t < 2; t++) {
        int row0 = 16*t + qr;
        float bb0 = b1s[row0], bb8 = b1s[row0+8];
        #pragma unroll
        for (int j = 0; j < 2; j++) {
            int N3 = 16*w8 + 8*j;
            *(float2*)&zrow[row0*SX + N3 + 2*qc] =
                make_float2(tf32f(gelu_f(d3[t][j][0] + bb0)),
                            tf32f(gelu_f(d3[t][j][1] + bb0)));
            *(float2*)&zrow[(row0+8)*SX + N3 + 2*qc] =
                make_float2(tf32f(gelu_f(d3[t][j][2] + bb8)),
                            tf32f(gelu_f(d3[t][j][3] + bb8)));
        }
    }
    __syncthreads();

    // ================= phase 4: fc2 + bias + gate*h1 ========================
    float d4[2][4][4];
    #pragma unroll
    for (int t = 0; t < 2; t++) {
        int row0 = 32*p + 16*t + qr;
        float bb0 = b2s[row0], bb8 = b2s[row0+8];
        #pragma unroll
        for (int j = 0; j < 4; j++) {
            d4[t][j][0] = bb0; d4[t][j][1] = bb0;
            d4[t][j][2] = bb8; d4[t][j][3] = bb8;
        }
    }
    #pragma unroll
    for (int ks = 0; ks < 4; ks++) {
        int k0 = ks * 8;
        uint32_t a[2][4];
        #pragma unroll
        for (int t = 0; t < 2; t++) {
            int R = 32*p + 16*t;
            float2 lo = *(const float2*)&f2A[(R+qr)*36 + k0 + 2*qc];
            float2 hi = *(const float2*)&f2A[(R+qr+8)*36 + k0 + 2*qc];
            a[t][0] = fbits(lo.x); a[t][1] = fbits(hi.x);
            a[t][2] = fbits(lo.y); a[t][3] = fbits(hi.y);
        }
        #pragma unroll
        for (int j = 0; j < 4; j++) {
            int N = 32*q + 8*j;
            uint32_t b0 = fbits(zrow[(k0+qc)*SX + N + qr]);
            uint32_t b1 = fbits(zrow[(k0+qc+4)*SX + N + qr]);
            mma8(d4[0][j], a[0][0], a[0][1], a[0][2], a[0][3], b0, b1);
            mma8(d4[1][j], a[1][0], a[1][1], a[1][2], a[1][3], b0, b1);
        }
    }
    // gate add, stage into h1s (free after phase3 reads)
    #pragma unroll
    for (int t = 0; t < 2; t++) {
        int row0 = 32*p + 16*t + qr;
        float g0 = gs[row0], g8 = gs[row0+8];
        #pragma unroll
        for (int j = 0; j < 4; j++) {
            int N = 32*q + 8*j;
            *(float2*)&h1s[hr*8704 + row0*SX + N + 2*qc] =
                make_float2(d4[t][j][0] + g0*h1r[t][j][0],
                            d4[t][j][1] + g0*h1r[t][j][1]);
            *(float2*)&h1s[hr*8704 + (row0+8)*SX + N + 2*qc] =
                make_float2(d4[t][j][2] + g8*h1r[t][j][2],
                            d4[t][j][3] + g8*h1r[t][j][3]);
        }
    }
    __syncthreads();

    // coalesced final store
    for (int i = tid; i < 4096; i += 512) {
        int hh = i >> 11, c = (i >> 5) & 63, w = (i & 31) * 4;
        float4 v = *(const float4*)&h1s[hh*8704 + c*SX + w];
        *(float4*)&out[(((size_t)b*64 + c)*128 + (2*hb + hh))*128 + w] = v;
    }
}

// ---------------- launch ----------------
extern "C" void kernel_launch(void* const* d_in, const int* in_sizes, int n_in,
                              void* d_out, int out_size) {
    const float* x    = (const float*)d_in[0];
    const float* wre  = (const float*)d_in[1];
    const float* wim  = (const float*)d_in[2];
    const float* wsk  = (const float*)d_in[3];
    const float* f1w  = (const float*)d_in[4];
    const float* f1b  = (const float*)d_in[5];
    const float* f2w  = (const float*)d_in[6];
    const float* f2b  = (const float*)d_in[7];
    const float* gate = (const float*)d_in[8];
    float* out = (float*)d_out;

    cudaFuncSetAttribute(k5_final, cudaFuncAttributeMaxDynamicSharedMemorySize,
                         K5_SMEM_FLOATS * (int)sizeof(float));

    k0_init<<<6, 512>>>();
    k1_dftW<<<1024, 384>>>(x);
    k2_dftH<<<1024, 288>>>();
    k3_mix<<<576, 512>>>(wre, wim);
    k4_idftH<<<1024, 128>>>();
    dim3 g5(64, 16);
    k5_final<<<g5, 512, K5_SMEM_FLOATS * sizeof(float)>>>(
        x, wsk, f1w, f1b, f2w, f2b, gate, out);
}